// round 15
// baseline (speedup 1.0000x reference)
#include <cuda_runtime.h>
#include <math.h>

typedef unsigned long long ull;

#define Bq   256
#define Tq   512
#define Dq   256
#define Hq   512
#define F1q  128
#define Oq   64
#define BHq  (Bq*Hq)
#define NBLK 128
#define NT   512                // threads per block (4 warps/SMSP)
#define RD   8                  // ring depth (slots)
#define RMASK (RD-1)
#define WST  68                 // W smem k-stride (floats)
#define AST  68                 // A chunk k-stride (floats)
#define ACHUNK (4*16*AST)       // one A staging buffer: 4 kz-groups x 16 k
#define SCH  (16*68)            // legacy chunk (head phase)
#define SMEM_ALL ((Hq*WST + 2*ACHUNK) * 4)   // 139264 + 34816 = 174,080 B

// ---------------- scratch (device globals: allocation-free rule) ----------------
__device__ float g_pre0r[RD*(size_t)BHq];   // 8-slot rings
__device__ float g_h0r [RD*(size_t)BHq];
__device__ float g_p1r [RD*(size_t)BHq];
__device__ float g_h1r [RD*(size_t)BHq];
__device__ float g_z1[Bq*F1q];
__device__ unsigned g_count;
__device__ volatile unsigned g_sense;

// per-(t,band) completion counters, each counts to 8 (one per col-tile block)
__device__ int f_pre0[Tq*4];
__device__ int f_g0 [Tq*4];
__device__ int f_g1 [Tq*4];
__device__ int f_g2 [Tq*4];
__device__ int f_fc1;

// ---------------- packed f32x2 helpers ----------------
__device__ __forceinline__ ull pack2(float lo, float hi)
{
    ull v;
    asm("mov.b64 %0, {%1, %2};" : "=l"(v) : "f"(lo), "f"(hi));
    return v;
}
__device__ __forceinline__ void unpack2(ull v, float &lo, float &hi)
{
    asm("mov.b64 {%0, %1}, %2;" : "=f"(lo), "=f"(hi) : "l"(v));
}
__device__ __forceinline__ void ffma2(ull &d, ull a, ull b)
{
    asm("fma.rn.f32x2 %0, %1, %2, %0;" : "+l"(d) : "l"(a), "l"(b));
}
__device__ __forceinline__ ull addp(ull a, ull b)
{
    ull d;
    asm("add.rn.f32x2 %0, %1, %2;" : "=l"(d) : "l"(a), "l"(b));
    return d;
}

// ---------------- sync primitives ----------------
__device__ __forceinline__ int ld_acq(const int* p)
{
    int v;
    asm volatile("ld.acquire.gpu.global.s32 %0, [%1];" : "=r"(v) : "l"(p) : "memory");
    return v;
}
__device__ __forceinline__ void wait8(const int* p)
{
    while (ld_acq(p) < 8) { }
}
__device__ __forceinline__ void pub_release(int* p)
{
    asm volatile("red.release.gpu.global.add.s32 [%0], %1;" :: "l"(p), "r"(1) : "memory");
}
#define BAR256() asm volatile("bar.sync 1, 256;" ::: "memory")

// sense-reversing grid barrier; called an even number of times per launch
__device__ __forceinline__ void grid_barrier(unsigned &sense)
{
    __syncthreads();
    if (threadIdx.x == 0) {
        unsigned ns = sense ^ 1u;
        if (atomicAdd(&g_count, 1u) == NBLK - 1u) {
            g_count = 0u;
            __threadfence();
            g_sense = ns;
        } else {
            while (g_sense != ns) { __nanosleep(32); }
        }
    }
    __syncthreads();
    sense ^= 1u;
}

// ======== K-split-4 / 8x4-per-thread GEMM (512 thr):  C64x64 = A(:,K) * Wsmem^T ====
// kz = tid>>7 (0..3) owns k-range [kz*K/4, ..); within a kz group of 128 threads,
// thread (py,px) = ((pos>>4), pos&15) computes the 8x4 tile rows py*8.., cols px*4..
// (partial sums). acc = 16 ull = 32 regs -> no spill at 512 threads (128-reg cap).
// 2 smem reduction rounds (4->2->1), final 64x64 staged (stride 68), readback 2x4.
// W smem layout per k row (WST floats): half-split off(n)=((n&4)?32:0)+((n>>3)<<2)+(n&3)
// -> float4 for cols 4px..4px+3 at offset (px&1)*32 + ((px>>1)<<2).
__device__ __forceinline__ void gemm64_kp(const float* __restrict__ A, int lda, int m0,
                                          const float* __restrict__ sW, int K,
                                          float* sA, float accf[2][4])
{
    const int tid = threadIdx.x;
    const int kz  = tid >> 7;           // 0..3
    const int pos = tid & 127;
    const int py  = pos >> 4, px = pos & 15;
    const int woff = ((px & 1) << 5) + ((px >> 1) << 2);
    // staging assignment: row = tid&63, s = tid>>6: g = s&3, kh = s>>2 (0..1)
    const int srow = tid & 63;
    const int sg   = (tid >> 6) & 3;
    const int skh  = (tid >> 8) & 1;
    const int K4 = K >> 2;
    const float* ap = A + (size_t)(m0 + srow) * lda + sg*K4 + (skh << 3);

    ull acc[4][4];
    #pragma unroll
    for (int i = 0; i < 4; ++i)
        #pragma unroll
        for (int j = 0; j < 4; ++j) acc[i][j] = 0ull;

    float4 pfA = __ldcg((const float4*)ap);
    float4 pfB = __ldcg((const float4*)(ap + 4));

    int buf = 0;
    for (int kc = 0; kc < K4; kc += 16, buf ^= 1) {
        float* sAb = sA + buf * ACHUNK;
        {
            // store 8 k-values for (sg, rows srow, k = kc + skh*8 + 0..7)
            float* d = sAb + (sg*16 + (skh << 3))*AST + srow;
            d[0*AST] = pfA.x; d[1*AST] = pfA.y; d[2*AST] = pfA.z; d[3*AST] = pfA.w;
            d[4*AST] = pfB.x; d[5*AST] = pfB.y; d[6*AST] = pfB.z; d[7*AST] = pfB.w;
        }
        __syncthreads();
        if (kc + 16 < K4) {
            pfA = __ldcg((const float4*)(ap + kc + 16));
            pfB = __ldcg((const float4*)(ap + kc + 20));
        }
        const float* sAk = sAb + kz*(16*AST) + (py << 3);
        const float* sWk = sW + (size_t)(kz*K4 + kc)*WST + woff;
        #pragma unroll
        for (int kk = 0; kk < 16; ++kk) {
            const float* ar = sAk + kk*AST;
            ulonglong2 aLo = *(const ulonglong2*)ar;        // rows +0,+1 | +2,+3
            ulonglong2 aHi = *(const ulonglong2*)(ar + 4);  // rows +4,+5 | +6,+7
            float4 w = *(const float4*)(sWk + kk*WST);      // cols 4px..4px+3
            ull b0 = pack2(w.x, w.x);
            ull b1 = pack2(w.y, w.y);
            ull b2 = pack2(w.z, w.z);
            ull b3 = pack2(w.w, w.w);
            ffma2(acc[0][0], aLo.x, b0); ffma2(acc[0][1], aLo.x, b1);
            ffma2(acc[0][2], aLo.x, b2); ffma2(acc[0][3], aLo.x, b3);
            ffma2(acc[1][0], aLo.y, b0); ffma2(acc[1][1], aLo.y, b1);
            ffma2(acc[1][2], aLo.y, b2); ffma2(acc[1][3], aLo.y, b3);
            ffma2(acc[2][0], aHi.x, b0); ffma2(acc[2][1], aHi.x, b1);
            ffma2(acc[2][2], aHi.x, b2); ffma2(acc[2][3], aHi.x, b3);
            ffma2(acc[3][0], aHi.y, b0); ffma2(acc[3][1], aHi.y, b1);
            ffma2(acc[3][2], aHi.y, b2); ffma2(acc[3][3], aHi.y, b3);
        }
    }
    __syncthreads();   // mainloop reads done; sA becomes the reduction buffer

    ull* rb = (ull*)sA;
    // round 1: kz 1,3 store (slot = (kz>>1)*128 + pos, 0..255), kz 0,2 add
    if (kz & 1) {
        const int slot = ((kz >> 1) << 7) + pos;
        #pragma unroll
        for (int i = 0; i < 4; ++i)
            #pragma unroll
            for (int j = 0; j < 4; ++j)
                rb[(i*4 + j)*256 + slot] = acc[i][j];
    }
    __syncthreads();
    if (!(kz & 1)) {
        const int slot = ((kz >> 1) << 7) + pos;
        #pragma unroll
        for (int i = 0; i < 4; ++i)
            #pragma unroll
            for (int j = 0; j < 4; ++j)
                acc[i][j] = addp(acc[i][j], rb[(i*4 + j)*256 + slot]);
    }
    __syncthreads();
    // round 2: kz 2 stores, kz 0 adds
    if (kz == 2) {
        #pragma unroll
        for (int i = 0; i < 4; ++i)
            #pragma unroll
            for (int j = 0; j < 4; ++j)
                rb[(i*4 + j)*128 + pos] = acc[i][j];
    }
    __syncthreads();
    if (kz == 0) {
        #pragma unroll
        for (int i = 0; i < 4; ++i)
            #pragma unroll
            for (int j = 0; j < 4; ++j)
                acc[i][j] = addp(acc[i][j], rb[(i*4 + j)*128 + pos]);
    }
    __syncthreads();
    // final: kz 0 stages the 64x64 result (row stride 68, 16B-aligned rows)
    float* fb = sA;
    if (kz == 0) {
        #pragma unroll
        for (int i = 0; i < 4; ++i) {
            #pragma unroll
            for (int j = 0; j < 4; ++j) {
                float lo, hi;
                unpack2(acc[i][j], lo, hi);
                fb[((py << 3) + 2*i    )*68 + (px << 2) + j] = lo;
                fb[((py << 3) + 2*i + 1)*68 + (px << 2) + j] = hi;
            }
        }
    }
    __syncthreads();
    // readback: thread (tx,ty) owns rows 2ty..2ty+1, cols 4tx..4tx+3
    const int tx = tid & 15, ty = tid >> 4;   // ty 0..31
    #pragma unroll
    for (int i = 0; i < 2; ++i) {
        float4 v = *(const float4*)&fb[((ty << 1) + i)*68 + (tx << 2)];
        accf[i][0] = v.x; accf[i][1] = v.y; accf[i][2] = v.z; accf[i][3] = v.w;
    }
    // caller's __syncthreads() orders these reads before any sA reuse
}

// preload one 64-row W tile into half-split layout sW[k*WST + off(n)]
__device__ __forceinline__ void preload_W(const float* __restrict__ W, int ldw, int n0,
                                          int K, float* sW)
{
    const int KQ = K >> 2;
    for (int i = threadIdx.x; i < (KQ << 6); i += NT) {
        int n  = i / KQ;
        int k4 = i - n * KQ;
        int off = ((n & 4) ? 32 : 0) + ((n >> 3) << 2) + (n & 3);
        float4 v = *(const float4*)(W + (size_t)(n0 + n) * ldw + (k4 << 2));
        sW[(4*k4+0)*WST + off] = v.x;
        sW[(4*k4+1)*WST + off] = v.y;
        sW[(4*k4+2)*WST + off] = v.z;
        sW[(4*k4+3)*WST + off] = v.w;
    }
}

// ------- head-phase chunked GEMM (threads 0-255 only; named barrier 1) -------
__device__ __forceinline__ void gemm64s(const float* __restrict__ A, int lda, int m0,
                                        const float* __restrict__ W, int ldw, int n0,
                                        int K, float* sA, float* sW, float accf[4][4])
{
    const int tid  = threadIdx.x;
    const int tx   = tid & 15, ty = tid >> 4;
    const int lrow = tid >> 2;
    const int lcg  = (tid & 3) << 2;
    const float* ap = A + (size_t)(m0 + lrow) * lda + lcg;
    const float* wp = W + (size_t)(n0 + lrow) * ldw + lcg;

    ull acc[2][4];
    #pragma unroll
    for (int i = 0; i < 2; ++i)
        #pragma unroll
        for (int j = 0; j < 4; ++j) acc[i][j] = 0ull;

    float4 av = __ldcg((const float4*)ap);
    float4 wv = *(const float4*)wp;

    int buf = 0;
    for (int kc = 0; kc < K; kc += 16, buf ^= 1) {
        float* sAb = sA + buf * SCH;
        float* sWb = sW + buf * SCH;
        sAb[(lcg+0)*68 + lrow] = av.x;
        sAb[(lcg+1)*68 + lrow] = av.y;
        sAb[(lcg+2)*68 + lrow] = av.z;
        sAb[(lcg+3)*68 + lrow] = av.w;
        sWb[(lcg+0)*68 + lrow] = wv.x;
        sWb[(lcg+1)*68 + lrow] = wv.y;
        sWb[(lcg+2)*68 + lrow] = wv.z;
        sWb[(lcg+3)*68 + lrow] = wv.w;
        BAR256();
        if (kc + 16 < K) {
            av = __ldcg((const float4*)(ap + kc + 16));
            wv = *(const float4*)(wp + kc + 16);
        }
        #pragma unroll
        for (int k = 0; k < 16; ++k) {
            ulonglong2 a = *(const ulonglong2*)(sAb + k*68 + (ty << 2));
            float4 w = *(const float4*)(sWb + k*68 + (tx << 2));
            ull b0 = pack2(w.x, w.x);
            ull b1 = pack2(w.y, w.y);
            ull b2 = pack2(w.z, w.z);
            ull b3 = pack2(w.w, w.w);
            ffma2(acc[0][0], a.x, b0); ffma2(acc[0][1], a.x, b1);
            ffma2(acc[0][2], a.x, b2); ffma2(acc[0][3], a.x, b3);
            ffma2(acc[1][0], a.y, b0); ffma2(acc[1][1], a.y, b1);
            ffma2(acc[1][2], a.y, b2); ffma2(acc[1][3], a.y, b3);
        }
        BAR256();
    }

    #pragma unroll
    for (int i = 0; i < 2; ++i)
        #pragma unroll
        for (int j = 0; j < 4; ++j)
            unpack2(acc[i][j], accf[2*i][j], accf[2*i + 1][j]);
}

// ========================= single persistent kernel =========================
__global__ void __launch_bounds__(NT, 1) k_all(const float* __restrict__ x,
                                               const float* __restrict__ Wih0,
                                               const float* __restrict__ bih0,
                                               const float* __restrict__ bhh0,
                                               const float* __restrict__ Whh0,
                                               const float* __restrict__ Wih1,
                                               const float* __restrict__ bih1,
                                               const float* __restrict__ bhh1,
                                               const float* __restrict__ Whh1,
                                               const float* __restrict__ Wf1,
                                               const float* __restrict__ bf1,
                                               const float* __restrict__ Wf2,
                                               const float* __restrict__ bf2,
                                               float* __restrict__ out)
{
    extern __shared__ __align__(16) float smem[];
    float* sW = smem;               // persistent W tile (half-split layout)
    float* sA = smem + Hq*WST;      // double-buffered A staging / reduction buffer

    const int tid   = threadIdx.x;
    const int blk   = blockIdx.x;
    const int band  = blk & 3;
    const int c     = (blk >> 2) & 7;
    const int group = blk >> 5;
    const int m0    = band << 6;
    const int n0    = c << 6;
    const int tx = tid & 15, ty = tid >> 4;     // epilogue tiling (2 rows x 4 cols)
    const int col = n0 + (tx << 2);
    unsigned sense = 0u;

    // ---- phase 0: reset flags (replay), preload W, zero t=-1 ring slots ----
    {
        int i = blk*NT + tid;
        if (i < Tq*4) { f_pre0[i] = 0; f_g0[i] = 0; f_g1[i] = 0; f_g2[i] = 0; }
        if (i == Tq*4) f_fc1 = 0;
    }
    if      (group == 0) preload_W(Whh0, Hq, n0, Hq, sW);
    else if (group == 1) preload_W(Wih1, Hq, n0, Hq, sW);
    else if (group == 2) preload_W(Whh1, Hq, n0, Hq, sW);
    else                 preload_W(Wih0, Dq, n0, Dq, sW);

    for (int i = blk*NT + tid; i < BHq; i += NBLK*NT) {
        g_h0r[(size_t)(RD-1)*BHq + i] = 0.f;
        g_h1r[(size_t)(RD-1)*BHq + i] = 0.f;
    }
    __threadfence();
    grid_barrier(sense);    // barrier #1

    float acc[2][4];

    // ---- phase 1: self-timed scan ----
    if (group == 3) {
        float4 b1 = *(const float4*)(bih0 + col);
        float4 b2 = *(const float4*)(bhh0 + col);
        for (int t = 0; t < Tq; ++t) {
            gemm64_kp(x + (size_t)t*Dq, Tq*Dq, m0, sW, Dq, sA, acc);
            __syncthreads();
            if (tid == 0 && t >= RD) wait8(&f_g0[(t-RD)*4 + band]);  // slot reusable
            __syncthreads();
            float* dst = g_pre0r + (size_t)(t & RMASK)*BHq;
            #pragma unroll
            for (int i = 0; i < 2; ++i) {
                int row = m0 + (ty << 1) + i;
                float4 o;
                o.x = acc[i][0] + b1.x + b2.x;
                o.y = acc[i][1] + b1.y + b2.y;
                o.z = acc[i][2] + b1.z + b2.z;
                o.w = acc[i][3] + b1.w + b2.w;
                *(float4*)(dst + (size_t)row*Hq + col) = o;
            }
            __syncthreads();
            if (tid == 0) pub_release(&f_pre0[t*4 + band]);
        }
    } else if (group == 0) {
        for (int t = 0; t < Tq; ++t) {
            if (tid == 0 && t >= 1) wait8(&f_g0[(t-1)*4 + band]);    // critical wait
            __syncthreads();
            const float* A = g_h0r + (size_t)((t-1) & RMASK)*BHq;
            gemm64_kp(A, Hq, m0, sW, Hq, sA, acc);
            __syncthreads();
            if (tid == 0) {
                wait8(&f_pre0[t*4 + band]);
                if (t >= RD) wait8(&f_g1[(t-RD)*4 + band]);
            }
            __syncthreads();
            const float* pin = g_pre0r + (size_t)(t & RMASK)*BHq;
            float* dst = g_h0r + (size_t)(t & RMASK)*BHq;
            #pragma unroll
            for (int i = 0; i < 2; ++i) {
                int row = m0 + (ty << 1) + i;
                float4 p = __ldcg((const float4*)(pin + (size_t)row*Hq + col));
                float4 o;
                o.x = tanhf(acc[i][0] + p.x);
                o.y = tanhf(acc[i][1] + p.y);
                o.z = tanhf(acc[i][2] + p.z);
                o.w = tanhf(acc[i][3] + p.w);
                *(float4*)(dst + (size_t)row*Hq + col) = o;
            }
            __syncthreads();
            if (tid == 0) pub_release(&f_g0[t*4 + band]);
        }
    } else if (group == 1) {
        float4 b1 = *(const float4*)(bih1 + col);
        float4 b2 = *(const float4*)(bhh1 + col);
        for (int t = 0; t < Tq; ++t) {
            if (tid == 0) wait8(&f_g0[t*4 + band]);
            __syncthreads();
            const float* A = g_h0r + (size_t)(t & RMASK)*BHq;
            gemm64_kp(A, Hq, m0, sW, Hq, sA, acc);
            __syncthreads();
            if (tid == 0 && t >= RD) wait8(&f_g2[(t-RD)*4 + band]);
            __syncthreads();
            float* dst = g_p1r + (size_t)(t & RMASK)*BHq;
            #pragma unroll
            for (int i = 0; i < 2; ++i) {
                int row = m0 + (ty << 1) + i;
                float4 o;
                o.x = acc[i][0] + b1.x + b2.x;
                o.y = acc[i][1] + b1.y + b2.y;
                o.z = acc[i][2] + b1.z + b2.z;
                o.w = acc[i][3] + b1.w + b2.w;
                *(float4*)(dst + (size_t)row*Hq + col) = o;
            }
            __syncthreads();
            if (tid == 0) pub_release(&f_g1[t*4 + band]);
        }
    } else {
        for (int t = 0; t < Tq; ++t) {
            if (tid == 0 && t >= 1) wait8(&f_g2[(t-1)*4 + band]);    // critical wait
            __syncthreads();
            const float* A = g_h1r + (size_t)((t-1) & RMASK)*BHq;
            gemm64_kp(A, Hq, m0, sW, Hq, sA, acc);
            __syncthreads();
            if (tid == 0) wait8(&f_g1[t*4 + band]);
            __syncthreads();
            const float* pin = g_p1r + (size_t)(t & RMASK)*BHq;
            float* dst = g_h1r + (size_t)(t & RMASK)*BHq;
            #pragma unroll
            for (int i = 0; i < 2; ++i) {
                int row = m0 + (ty << 1) + i;
                float4 p = __ldcg((const float4*)(pin + (size_t)row*Hq + col));
                float4 o;
                o.x = tanhf(acc[i][0] + p.x);
                o.y = tanhf(acc[i][1] + p.y);
                o.z = tanhf(acc[i][2] + p.z);
                o.w = tanhf(acc[i][3] + p.w);
                *(float4*)(dst + (size_t)row*Hq + col) = o;
            }
            __syncthreads();
            if (tid == 0) pub_release(&f_g2[t*4 + band]);
        }
    }

    __threadfence();        // final ring stores visible to head readers
    grid_barrier(sense);    // barrier #2 (sense back to 0)

    // ---- phase 2: head on threads 0-255 (named barrier); others exit ----
    if (tid < 256) {
        float* hA = smem;
        float* hW = smem + 2*SCH;
        float hacc[4][4];
        const int htx = tid & 15, hty = tid >> 4;

        if (blk < 8) {
            const int hm0 = (blk & 3) << 6;
            const int hn0 = (blk >> 2) << 6;
            const float* A = g_h1r + (size_t)((Tq-1) & RMASK)*BHq;
            gemm64s(A, Hq, hm0, Wf1, Hq, hn0, Hq, hA, hW, hacc);
            const int hcol = hn0 + (htx << 2);
            float4 b = *(const float4*)(bf1 + hcol);
            #pragma unroll
            for (int i = 0; i < 4; ++i) {
                int row = hm0 + (hty << 2) + i;
                float4 o;
                o.x = fmaxf(hacc[i][0] + b.x, 0.f);
                o.y = fmaxf(hacc[i][1] + b.y, 0.f);
                o.z = fmaxf(hacc[i][2] + b.z, 0.f);
                o.w = fmaxf(hacc[i][3] + b.w, 0.f);
                *(float4*)(g_z1 + (size_t)row*F1q + hcol) = o;
            }
            BAR256();
            if (tid == 0) pub_release(&f_fc1);
        } else if (blk < 12) {
            if (tid == 0) wait8(&f_fc1);
            BAR256();
            const int hm0 = (blk - 8) << 6;
            gemm64s(g_z1, F1q, hm0, Wf2, F1q, 0, F1q, hA, hW, hacc);
            const int hcol = htx << 2;
            float4 b = *(const float4*)(bf2 + hcol);
            #pragma unroll
            for (int i = 0; i < 4; ++i) {
                int row = hm0 + (hty << 2) + i;
                float4 o;
                o.x = hacc[i][0] + b.x;
                o.y = hacc[i][1] + b.y;
                o.z = hacc[i][2] + b.z;
                o.w = hacc[i][3] + b.w;
                *(float4*)(out + (size_t)row*Oq + hcol) = o;
            }
        }
    }
}

// ---------------- launch ----------------
extern "C" void kernel_launch(void* const* d_in, const int* in_sizes, int n_in,
                              void* d_out, int out_size)
{
    (void)in_sizes; (void)n_in; (void)out_size;
    const float* x    = (const float*)d_in[0];
    const float* Wih0 = (const float*)d_in[1];
    const float* Whh0 = (const float*)d_in[2];
    const float* bih0 = (const float*)d_in[3];
    const float* bhh0 = (const float*)d_in[4];
    const float* Wih1 = (const float*)d_in[5];
    const float* Whh1 = (const float*)d_in[6];
    const float* bih1 = (const float*)d_in[7];
    const float* bhh1 = (const float*)d_in[8];
    const float* Wf1  = (const float*)d_in[9];
    const float* bf1  = (const float*)d_in[10];
    const float* Wf2  = (const float*)d_in[11];
    const float* bf2  = (const float*)d_in[12];
    float* out = (float*)d_out;

    cudaFuncSetAttribute(k_all, cudaFuncAttributeMaxDynamicSharedMemorySize, SMEM_ALL);

    k_all<<<NBLK, NT, SMEM_ALL>>>(x, Wih0, bih0, bhh0, Whh0,
                                  Wih1, bih1, bhh1, Whh1,
                                  Wf1, bf1, Wf2, bf2, out);
}

// round 17
// speedup vs baseline: 1.3926x; 1.3926x over previous
#include <cuda_runtime.h>
#include <cuda_bf16.h>
#include <math.h>

typedef unsigned long long ull;
typedef unsigned int uint32;

#define Bq   256
#define Tq   512
#define Dq   256
#define Hq   512
#define F1q  128
#define Oq   64
#define BHq  (Bq*Hq)
#define NBLK 128
#define NT   256
#define RD   8
#define RMASK 7

// smem word (uint32) layout
#define WROW   260              // W plane row stride (words); 260%32==4 -> conflict-free
#define WPLW   (64*WROW)        // 16640 words per W plane
#define ABASE  (2*WPLW)         // 33280: A region start
#define AROW   68               // A row stride (words); 68%32==4
#define APLW   (64*AROW)        // 4352 words per A plane
#define SMEM_ALL ((ABASE + 2*APLW) * 4)   // 167,936 B
#define SCH  (16*68)            // head-phase staging chunk (floats)

// ---------------- device scratch ----------------
__device__ __nv_bfloat16 g_xhi[(size_t)Bq*Tq*Dq];
__device__ __nv_bfloat16 g_xlo[(size_t)Bq*Tq*Dq];
__device__ __nv_bfloat16 g_h0hi[RD*(size_t)BHq];
__device__ __nv_bfloat16 g_h0lo[RD*(size_t)BHq];
__device__ __nv_bfloat16 g_h1hi[RD*(size_t)BHq];
__device__ __nv_bfloat16 g_h1lo[RD*(size_t)BHq];
__device__ float g_pre0r[RD*(size_t)BHq];
__device__ float g_p1r [RD*(size_t)BHq];
__device__ float g_hlast[BHq];
__device__ float g_z1[Bq*F1q];
__device__ unsigned g_count;
__device__ volatile unsigned g_sense;

// per-(t,band) counters, count to 8 (one per col-tile block)
__device__ int f_pre0[Tq*4];
__device__ int f_g0 [Tq*4];
__device__ int f_g1 [Tq*4];
__device__ int f_g2 [Tq*4];
__device__ int f_fc1;

// ---------------- helpers ----------------
__device__ __forceinline__ ull pack2(float lo, float hi)
{
    ull v; asm("mov.b64 %0, {%1, %2};" : "=l"(v) : "f"(lo), "f"(hi)); return v;
}
__device__ __forceinline__ void unpack2(ull v, float &lo, float &hi)
{
    asm("mov.b64 {%0, %1}, %2;" : "=f"(lo), "=f"(hi) : "l"(v));
}
__device__ __forceinline__ void ffma2(ull &d, ull a, ull b)
{
    asm("fma.rn.f32x2 %0, %1, %2, %0;" : "+l"(d) : "l"(a), "l"(b));
}
// split (a,b) -> packed bf16 hi pair + lo residual pair
__device__ __forceinline__ void split2(float a, float b, uint32 &hi, uint32 &lo)
{
    __nv_bfloat16 ha = __float2bfloat16(a), hb = __float2bfloat16(b);
    hi = ((uint32)__bfloat16_as_ushort(hb) << 16) | (uint32)__bfloat16_as_ushort(ha);
    float ra = a - __bfloat162float(ha), rb = b - __bfloat162float(hb);
    __nv_bfloat16 la = __float2bfloat16(ra), lb = __float2bfloat16(rb);
    lo = ((uint32)__bfloat16_as_ushort(lb) << 16) | (uint32)__bfloat16_as_ushort(la);
}
// warp HMMA: D(16x8,f32) += A(16x16 bf16, row) * B(16x8 bf16, col-from-[n][k])
__device__ __forceinline__ void mma_bf16(float c[4], uint32 a0, uint32 a1, uint32 a2,
                                         uint32 a3, uint32 b0, uint32 b1)
{
    asm volatile("mma.sync.aligned.m16n8k16.row.col.f32.bf16.bf16.f32 "
        "{%0,%1,%2,%3}, {%4,%5,%6,%7}, {%8,%9}, {%0,%1,%2,%3};"
        : "+f"(c[0]), "+f"(c[1]), "+f"(c[2]), "+f"(c[3])
        : "r"(a0), "r"(a1), "r"(a2), "r"(a3), "r"(b0), "r"(b1));
}

// ---------------- sync primitives ----------------
__device__ __forceinline__ int ld_acq(const int* p)
{
    int v;
    asm volatile("ld.acquire.gpu.global.s32 %0, [%1];" : "=r"(v) : "l"(p) : "memory");
    return v;
}
__device__ __forceinline__ void wait8(const int* p) { while (ld_acq(p) < 8) { } }
__device__ __forceinline__ void pub_release(int* p)
{
    asm volatile("red.release.gpu.global.add.s32 [%0], %1;" :: "l"(p), "r"(1) : "memory");
}
__device__ __forceinline__ void grid_barrier(unsigned &sense)
{
    __syncthreads();
    if (threadIdx.x == 0) {
        unsigned ns = sense ^ 1u;
        if (atomicAdd(&g_count, 1u) == NBLK - 1u) {
            g_count = 0u; __threadfence(); g_sense = ns;
        } else {
            while (g_sense != ns) { __nanosleep(32); }
        }
    }
    __syncthreads();
    sense ^= 1u;
}

// ======== bf16-split mma.sync GEMM: C(64x64 f32 frags) = A(64xK) * W^T ========
// 8 warps: warp w -> rows (w&3)*16.., cols (w>>2)*32.. ; per k16: 3 HMMA per n8
// (hi*hi + hi*lo + lo*hi). A staged per 128-k chunk from gmem bf16 planes.
__device__ __forceinline__ void gemm_mma(const __nv_bfloat16* __restrict__ ahi,
                                         const __nv_bfloat16* __restrict__ alo,
                                         size_t lda, int K,
                                         uint32* sw, float c[4][4])
{
    const int tid = threadIdx.x;
    const int w = tid >> 5, lane = tid & 31;
    const int g = lane >> 2, p0 = lane & 3;
    const int rowg = (w & 3) << 4, colg = (w >> 2) << 5;
    uint32* sa = sw + ABASE;

    #pragma unroll
    for (int nt = 0; nt < 4; ++nt)
        #pragma unroll
        for (int j = 0; j < 4; ++j) c[nt][j] = 0.f;

    // staging role: plane = tid>>7, row = (tid&127)>>1, half = tid&1
    const int spl = tid >> 7, srow = (tid & 127) >> 1, shalf = tid & 1;
    const __nv_bfloat16* sbase = (spl ? alo : ahi) + (size_t)srow*lda + shalf*64;
    uint32* sdst = sa + spl*APLW + srow*AROW + shalf*32;

    for (int kc = 0; kc < K; kc += 128) {
        __syncthreads();                        // prior chunk's readers done
        {
            const __nv_bfloat16* src = sbase + kc;
            #pragma unroll
            for (int j = 0; j < 8; ++j) {
                uint4 v = __ldcg((const uint4*)(src + 8*j));
                *(uint4*)(sdst + 4*j) = v;
            }
        }
        __syncthreads();
        const int pbc = kc >> 1;
        #pragma unroll
        for (int b = 0; b < 8; ++b) {
            const int ap = 8*b + p0;
            const uint32* ar0 = sa + (rowg + g)*AROW + ap;
            const uint32* ar1 = sa + (rowg + g + 8)*AROW + ap;
            uint32 aH0 = ar0[0],      aH1 = ar1[0];
            uint32 aH2 = ar0[4],      aH3 = ar1[4];
            uint32 aL0 = ar0[APLW],   aL1 = ar1[APLW];
            uint32 aL2 = ar0[APLW+4], aL3 = ar1[APLW+4];
            const int pb = pbc + 8*b + p0;
            #pragma unroll
            for (int nt = 0; nt < 4; ++nt) {
                const int n = colg + 8*nt + g;
                const uint32* wr = sw + n*WROW + pb;
                uint32 bH0 = wr[0],      bH1 = wr[4];
                uint32 bL0 = wr[WPLW],   bL1 = wr[WPLW+4];
                mma_bf16(c[nt], aH0, aH1, aH2, aH3, bH0, bH1);
                mma_bf16(c[nt], aH0, aH1, aH2, aH3, bL0, bL1);
                mma_bf16(c[nt], aL0, aL1, aL2, aL3, bH0, bH1);
            }
        }
    }
    __syncthreads();   // compute reads done before caller reuses/restages sA
}

// preload one 64-row W tile into smem bf16 planes [n][pair], stride WROW
__device__ __forceinline__ void preload_W(const float* __restrict__ W, int ldw, int n0,
                                          int K, uint32* sw)
{
    const int kT4 = K >> 2;
    for (int i = threadIdx.x; i < (kT4 << 6); i += NT) {
        int n = i / kT4, q = i - n*kT4, k = q << 2;
        float4 v = *(const float4*)(W + (size_t)(n0 + n)*ldw + k);
        uint32 h01, l01, h23, l23;
        split2(v.x, v.y, h01, l01);
        split2(v.z, v.w, h23, l23);
        uint32* d = sw + n*WROW + (k >> 1);
        d[0] = h01; d[1] = h23;
        d[WPLW] = l01; d[WPLW + 1] = l23;
    }
}

// ---------------- head-phase fp32 SIMT GEMM (proven core) ----------------
__device__ __forceinline__ void gemm64s(const float* __restrict__ A, int lda, int m0,
                                        const float* __restrict__ W, int ldw, int n0,
                                        int K, float* sA, float* sW, float accf[4][4])
{
    const int tid  = threadIdx.x;
    const int tx   = tid & 15, ty = tid >> 4;
    const int lrow = tid >> 2;
    const int lcg  = (tid & 3) << 2;
    const float* ap = A + (size_t)(m0 + lrow) * lda + lcg;
    const float* wp = W + (size_t)(n0 + lrow) * ldw + lcg;

    ull acc[2][4];
    #pragma unroll
    for (int i = 0; i < 2; ++i)
        #pragma unroll
        for (int j = 0; j < 4; ++j) acc[i][j] = 0ull;

    float4 av = __ldcg((const float4*)ap);
    float4 wv = *(const float4*)wp;

    int buf = 0;
    for (int kc = 0; kc < K; kc += 16, buf ^= 1) {
        float* sAb = sA + buf * SCH;
        float* sWb = sW + buf * SCH;
        sAb[(lcg+0)*68 + lrow] = av.x;
        sAb[(lcg+1)*68 + lrow] = av.y;
        sAb[(lcg+2)*68 + lrow] = av.z;
        sAb[(lcg+3)*68 + lrow] = av.w;
        sWb[(lcg+0)*68 + lrow] = wv.x;
        sWb[(lcg+1)*68 + lrow] = wv.y;
        sWb[(lcg+2)*68 + lrow] = wv.z;
        sWb[(lcg+3)*68 + lrow] = wv.w;
        __syncthreads();
        if (kc + 16 < K) {
            av = __ldcg((const float4*)(ap + kc + 16));
            wv = *(const float4*)(wp + kc + 16);
        }
        #pragma unroll
        for (int k = 0; k < 16; ++k) {
            ulonglong2 a = *(const ulonglong2*)(sAb + k*68 + (ty << 2));
            float4 w = *(const float4*)(sWb + k*68 + (tx << 2));
            ull b0 = pack2(w.x, w.x);
            ull b1 = pack2(w.y, w.y);
            ull b2 = pack2(w.z, w.z);
            ull b3 = pack2(w.w, w.w);
            ffma2(acc[0][0], a.x, b0); ffma2(acc[0][1], a.x, b1);
            ffma2(acc[0][2], a.x, b2); ffma2(acc[0][3], a.x, b3);
            ffma2(acc[1][0], a.y, b0); ffma2(acc[1][1], a.y, b1);
            ffma2(acc[1][2], a.y, b2); ffma2(acc[1][3], a.y, b3);
        }
        __syncthreads();
    }

    #pragma unroll
    for (int i = 0; i < 2; ++i)
        #pragma unroll
        for (int j = 0; j < 4; ++j)
            unpack2(acc[i][j], accf[2*i][j], accf[2*i + 1][j]);
}

// ========================= single persistent kernel =========================
__global__ void __launch_bounds__(NT) k_all(const float* __restrict__ x,
                                            const float* __restrict__ Wih0,
                                            const float* __restrict__ bih0,
                                            const float* __restrict__ bhh0,
                                            const float* __restrict__ Whh0,
                                            const float* __restrict__ Wih1,
                                            const float* __restrict__ bih1,
                                            const float* __restrict__ bhh1,
                                            const float* __restrict__ Whh1,
                                            const float* __restrict__ Wf1,
                                            const float* __restrict__ bf1,
                                            const float* __restrict__ Wf2,
                                            const float* __restrict__ bf2,
                                            float* __restrict__ out)
{
    extern __shared__ __align__(16) uint32 smemw[];

    const int tid   = threadIdx.x;
    const int blk   = blockIdx.x;
    const int band  = blk & 3;          // 4 bands of 64 rows
    const int cidx  = (blk >> 2) & 7;   // 8 col tiles of 64
    const int group = blk >> 5;         // 0..3
    const int m0    = band << 6;
    const int n0    = cidx << 6;
    unsigned sense = 0u;

    // warp/lane geometry for mma epilogues
    const int w = tid >> 5, lane = tid & 31;
    const int g = lane >> 2, p0 = lane & 3;
    const int rowg = (w & 3) << 4, colg = (w >> 2) << 5;
    const int gr0 = m0 + rowg + g;      // frag row 0 (global)
    const int gcb = colg + 2*p0;        // frag col base within tile (+8*nt)

    // ---- phase 0: init ----
    {
        int i = blk*NT + tid;
        if (i < Tq*4) { f_pre0[i] = 0; f_g0[i] = 0; f_g1[i] = 0; f_g2[i] = 0; }
        if (i == Tq*4) f_fc1 = 0;
    }
    // split x into bf16 planes
    {
        const size_t n4 = ((size_t)Bq*Tq*Dq) >> 2;
        for (size_t i4 = (size_t)blk*NT + tid; i4 < n4; i4 += (size_t)NBLK*NT) {
            float4 v = *(const float4*)(x + (i4 << 2));
            uint32 h01, l01, h23, l23;
            split2(v.x, v.y, h01, l01);
            split2(v.z, v.w, h23, l23);
            ((uint2*)g_xhi)[i4] = make_uint2(h01, h23);
            ((uint2*)g_xlo)[i4] = make_uint2(l01, l23);
        }
    }
    if      (group == 0) preload_W(Whh0, Hq, n0, Hq, smemw);
    else if (group == 1) preload_W(Wih1, Hq, n0, Hq, smemw);
    else if (group == 2) preload_W(Whh1, Hq, n0, Hq, smemw);
    else                 preload_W(Wih0, Dq, n0, Dq, smemw);

    // zero t=-1 (slot RD-1) of h rings
    {
        const size_t base = ((size_t)(RD-1)*BHq) >> 1;
        for (size_t i = (size_t)blk*NT + tid; i < (BHq >> 1); i += (size_t)NBLK*NT) {
            ((uint32*)g_h0hi)[base + i] = 0u;
            ((uint32*)g_h0lo)[base + i] = 0u;
            ((uint32*)g_h1hi)[base + i] = 0u;
            ((uint32*)g_h1lo)[base + i] = 0u;
        }
    }
    __threadfence();
    grid_barrier(sense);    // barrier #1

    float c[4][4];

    // ---- phase 1: self-timed scan ----
    if (group == 3) {
        for (int t = 0; t < Tq; ++t) {
            gemm_mma(g_xhi + (size_t)m0*Tq*Dq + (size_t)t*Dq,
                     g_xlo + (size_t)m0*Tq*Dq + (size_t)t*Dq,
                     (size_t)Tq*Dq, Dq, smemw, c);
            if (tid == 0 && t >= RD) wait8(&f_g0[(t-RD)*4 + band]);
            __syncthreads();
            float* dst = g_pre0r + (size_t)(t & RMASK)*BHq;
            #pragma unroll
            for (int nt = 0; nt < 4; ++nt) {
                const int gc = n0 + gcb + 8*nt;
                float2 b1 = *(const float2*)(bih0 + gc);
                float2 b2 = *(const float2*)(bhh0 + gc);
                float2 o0, o1;
                o0.x = c[nt][0] + b1.x + b2.x; o0.y = c[nt][1] + b1.y + b2.y;
                o1.x = c[nt][2] + b1.x + b2.x; o1.y = c[nt][3] + b1.y + b2.y;
                *(float2*)(dst + (size_t)gr0*Hq + gc)     = o0;
                *(float2*)(dst + (size_t)(gr0+8)*Hq + gc) = o1;
            }
            __syncthreads();
            if (tid == 0) pub_release(&f_pre0[t*4 + band]);
        }
    } else if (group == 0) {
        for (int t = 0; t < Tq; ++t) {
            if (tid == 0 && t >= 1) wait8(&f_g0[(t-1)*4 + band]);
            __syncthreads();
            const size_t sp = (size_t)((t-1) & RMASK)*BHq + (size_t)m0*Hq;
            gemm_mma(g_h0hi + sp, g_h0lo + sp, Hq, Hq, smemw, c);
            if (tid == 0) {
                wait8(&f_pre0[t*4 + band]);
                if (t >= RD) wait8(&f_g1[(t-RD)*4 + band]);
            }
            __syncthreads();
            const int s = t & RMASK;
            const float* pp = g_pre0r + (size_t)s*BHq;
            uint32* hh = (uint32*)g_h0hi + (((size_t)s*BHq) >> 1);
            uint32* ll = (uint32*)g_h0lo + (((size_t)s*BHq) >> 1);
            #pragma unroll
            for (int nt = 0; nt < 4; ++nt) {
                const int gc = n0 + gcb + 8*nt;
                float2 pa = __ldcg((const float2*)(pp + (size_t)gr0*Hq + gc));
                float2 pb = __ldcg((const float2*)(pp + (size_t)(gr0+8)*Hq + gc));
                float a0 = tanhf(c[nt][0] + pa.x), a1 = tanhf(c[nt][1] + pa.y);
                float a2 = tanhf(c[nt][2] + pb.x), a3 = tanhf(c[nt][3] + pb.y);
                uint32 h01, l01, h23, l23;
                split2(a0, a1, h01, l01);
                split2(a2, a3, h23, l23);
                hh[((size_t)gr0*Hq + gc) >> 1]     = h01;
                ll[((size_t)gr0*Hq + gc) >> 1]     = l01;
                hh[((size_t)(gr0+8)*Hq + gc) >> 1] = h23;
                ll[((size_t)(gr0+8)*Hq + gc) >> 1] = l23;
            }
            __syncthreads();
            if (tid == 0) pub_release(&f_g0[t*4 + band]);
        }
    } else if (group == 1) {
        for (int t = 0; t < Tq; ++t) {
            if (tid == 0) wait8(&f_g0[t*4 + band]);
            __syncthreads();
            const size_t sp = (size_t)(t & RMASK)*BHq + (size_t)m0*Hq;
            gemm_mma(g_h0hi + sp, g_h0lo + sp, Hq, Hq, smemw, c);
            if (tid == 0 && t >= RD) wait8(&f_g2[(t-RD)*4 + band]);
            __syncthreads();
            float* dst = g_p1r + (size_t)(t & RMASK)*BHq;
            #pragma unroll
            for (int nt = 0; nt < 4; ++nt) {
                const int gc = n0 + gcb + 8*nt;
                float2 b1 = *(const float2*)(bih1 + gc);
                float2 b2 = *(const float2*)(bhh1 + gc);
                float2 o0, o1;
                o0.x = c[nt][0] + b1.x + b2.x; o0.y = c[nt][1] + b1.y + b2.y;
                o1.x = c[nt][2] + b1.x + b2.x; o1.y = c[nt][3] + b1.y + b2.y;
                *(float2*)(dst + (size_t)gr0*Hq + gc)     = o0;
                *(float2*)(dst + (size_t)(gr0+8)*Hq + gc) = o1;
            }
            __syncthreads();
            if (tid == 0) pub_release(&f_g1[t*4 + band]);
        }
    } else {
        for (int t = 0; t < Tq; ++t) {
            if (tid == 0 && t >= 1) wait8(&f_g2[(t-1)*4 + band]);
            __syncthreads();
            const size_t sp = (size_t)((t-1) & RMASK)*BHq + (size_t)m0*Hq;
            gemm_mma(g_h1hi + sp, g_h1lo + sp, Hq, Hq, smemw, c);
            if (tid == 0) wait8(&f_g1[t*4 + band]);
            __syncthreads();
            const int s = t & RMASK;
            const float* pp = g_p1r + (size_t)s*BHq;
            uint32* hh = (uint32*)g_h1hi + (((size_t)s*BHq) >> 1);
            uint32* ll = (uint32*)g_h1lo + (((size_t)s*BHq) >> 1);
            #pragma unroll
            for (int nt = 0; nt < 4; ++nt) {
                const int gc = n0 + gcb + 8*nt;
                float2 pa = __ldcg((const float2*)(pp + (size_t)gr0*Hq + gc));
                float2 pb = __ldcg((const float2*)(pp + (size_t)(gr0+8)*Hq + gc));
                float a0 = tanhf(c[nt][0] + pa.x), a1 = tanhf(c[nt][1] + pa.y);
                float a2 = tanhf(c[nt][2] + pb.x), a3 = tanhf(c[nt][3] + pb.y);
                uint32 h01, l01, h23, l23;
                split2(a0, a1, h01, l01);
                split2(a2, a3, h23, l23);
                hh[((size_t)gr0*Hq + gc) >> 1]     = h01;
                ll[((size_t)gr0*Hq + gc) >> 1]     = l01;
                hh[((size_t)(gr0+8)*Hq + gc) >> 1] = h23;
                ll[((size_t)(gr0+8)*Hq + gc) >> 1] = l23;
                if (t == Tq - 1) {
                    float2 f0; f0.x = a0; f0.y = a1;
                    float2 f1; f1.x = a2; f1.y = a3;
                    *(float2*)(g_hlast + (size_t)gr0*Hq + gc)     = f0;
                    *(float2*)(g_hlast + (size_t)(gr0+8)*Hq + gc) = f1;
                }
            }
            __syncthreads();
            if (tid == 0) pub_release(&f_g2[t*4 + band]);
        }
    }

    __threadfence();
    grid_barrier(sense);    // barrier #2 (sense back to 0)

    // ---- phase 2: head (fp32 SIMT; smem reused) ----
    float* hA = (float*)smemw;
    float* hW = (float*)smemw + 2*SCH;
    float acc[4][4];
    const int tx = tid & 15, ty = tid >> 4;

    if (blk < 8) {
        const int hm0 = (blk & 3) << 6;
        const int hn0 = (blk >> 2) << 6;
        gemm64s(g_hlast, Hq, hm0, Wf1, Hq, hn0, Hq, hA, hW, acc);
        const int hcol = hn0 + (tx << 2);
        float4 b = *(const float4*)(bf1 + hcol);
        #pragma unroll
        for (int i = 0; i < 4; ++i) {
            int row = hm0 + (ty << 2) + i;
            float4 o;
            o.x = fmaxf(acc[i][0] + b.x, 0.f);
            o.y = fmaxf(acc[i][1] + b.y, 0.f);
            o.z = fmaxf(acc[i][2] + b.z, 0.f);
            o.w = fmaxf(acc[i][3] + b.w, 0.f);
            *(float4*)(g_z1 + (size_t)row*F1q + hcol) = o;
        }
        __syncthreads();
        if (tid == 0) pub_release(&f_fc1);
    } else if (blk < 12) {
        if (tid == 0) wait8(&f_fc1);
        __syncthreads();
        const int hm0 = (blk - 8) << 6;
        gemm64s(g_z1, F1q, hm0, Wf2, F1q, 0, F1q, hA, hW, acc);
        const int hcol = tx << 2;
        float4 b = *(const float4*)(bf2 + hcol);
        #pragma unroll
        for (int i = 0; i < 4; ++i) {
            int row = hm0 + (ty << 2) + i;
            float4 o;
            o.x = acc[i][0] + b.x;
            o.y = acc[i][1] + b.y;
            o.z = acc[i][2] + b.z;
            o.w = acc[i][3] + b.w;
            *(float4*)(out + (size_t)row*Oq + hcol) = o;
        }
    }
}

// ---------------- launch ----------------
extern "C" void kernel_launch(void* const* d_in, const int* in_sizes, int n_in,
                              void* d_out, int out_size)
{
    (void)in_sizes; (void)n_in; (void)out_size;
    const float* x    = (const float*)d_in[0];
    const float* Wih0 = (const float*)d_in[1];
    const float* Whh0 = (const float*)d_in[2];
    const float* bih0 = (const float*)d_in[3];
    const float* bhh0 = (const float*)d_in[4];
    const float* Wih1 = (const float*)d_in[5];
    const float* Whh1 = (const float*)d_in[6];
    const float* bih1 = (const float*)d_in[7];
    const float* bhh1 = (const float*)d_in[8];
    const float* Wf1  = (const float*)d_in[9];
    const float* bf1  = (const float*)d_in[10];
    const float* Wf2  = (const float*)d_in[11];
    const float* bf2  = (const float*)d_in[12];
    float* out = (float*)d_out;

    cudaFuncSetAttribute(k_all, cudaFuncAttributeMaxDynamicSharedMemorySize, SMEM_ALL);

    k_all<<<NBLK, NT, SMEM_ALL>>>(x, Wih0, bih0, bhh0, Whh0,
                                  Wih1, bih1, bhh1, Whh1,
                                  Wf1, bf1, Wf2, bf2, out);
}